// round 5
// baseline (speedup 1.0000x reference)
#include <cuda_runtime.h>
#include <cuda_bf16.h>
#include <math.h>
#include <stdint.h>

#define B_    128
#define SEQ_  200
#define VOCAB_ 1400
#define D_    256
#define H_    256
#define NCLS_ 128
#define G4H   1024
#define KP_IN 1408            // 1400 padded to multiple of 32

// ---------------- scratch (static __device__, no allocations) ----------------
__device__ float g_embedded[B_ * SEQ_ * D_];
__device__ float g_ux1[B_ * SEQ_ * G4H];
__device__ float g_ux2[B_ * SEQ_ * G4H];
__device__ float g_out1[B_ * SEQ_ * H_];
__device__ float g_out2[B_ * SEQ_ * H_];
__device__ float g_beta[B_ * SEQ_ * H_];
__device__ float g_hbuf[2 * 2 * B_ * H_];
__device__ float g_cbuf[2 * 2 * B_ * H_];
__device__ float g_alpha[B_ * SEQ_];
__device__ float g_ctx[B_ * D_];
__device__ unsigned g_cnt[16];
__device__ volatile unsigned g_gen[16];

// bf16 hi/lo operand buffers (plain row-major [Rows][Kp])
__device__ __nv_bfloat16 ga_in_hi[B_ * SEQ_ * KP_IN];
__device__ __nv_bfloat16 ga_in_lo[B_ * SEQ_ * KP_IN];
__device__ __nv_bfloat16 gb_emb_hi[D_ * KP_IN];
__device__ __nv_bfloat16 gb_emb_lo[D_ * KP_IN];
__device__ __nv_bfloat16 ga_e_hi[B_ * SEQ_ * D_];
__device__ __nv_bfloat16 ga_e_lo[B_ * SEQ_ * D_];
__device__ __nv_bfloat16 gb_u1_hi[G4H * H_];
__device__ __nv_bfloat16 gb_u1_lo[G4H * H_];
__device__ __nv_bfloat16 gb_u2_hi[G4H * H_];
__device__ __nv_bfloat16 gb_u2_lo[G4H * H_];
__device__ __nv_bfloat16 gb_wb_hi[H_ * H_];
__device__ __nv_bfloat16 gb_wb_lo[H_ * H_];
__device__ __nv_bfloat16 ga_o2_hi[B_ * SEQ_ * H_];
__device__ __nv_bfloat16 ga_o2_lo[B_ * SEQ_ * H_];

// ---------------- helpers ----------------
__device__ __forceinline__ uint32_t smem_u32(const void* p) {
    uint32_t a;
    asm("{ .reg .u64 t; cvta.to.shared.u64 t, %1; cvt.u32.u64 %0, t; }" : "=r"(a) : "l"(p));
    return a;
}
#define CP_ASYNC16(saddr, gptr) \
    asm volatile("cp.async.cg.shared.global [%0], [%1], 16;" :: "r"(saddr), "l"(gptr) : "memory")
#define CP_COMMIT() asm volatile("cp.async.commit_group;" ::: "memory")
#define CP_WAIT0()  asm volatile("cp.async.wait_group 0;" ::: "memory")

__device__ __forceinline__ void mma_bf16(float* c, const uint32_t* a, uint32_t b0, uint32_t b1) {
    asm volatile(
        "mma.sync.aligned.m16n8k16.row.col.f32.bf16.bf16.f32 "
        "{%0,%1,%2,%3}, {%4,%5,%6,%7}, {%8,%9}, {%0,%1,%2,%3};"
        : "+f"(c[0]), "+f"(c[1]), "+f"(c[2]), "+f"(c[3])
        : "r"(a[0]), "r"(a[1]), "r"(a[2]), "r"(a[3]), "r"(b0), "r"(b1));
}

// ---------------- hi/lo bf16 conversion (row-major, zero-padded K) ----------------
// element(row,k) = trans ? src[k*ld + row] : src[row*ld + k]; k >= Ksrc -> 0
__global__ void conv_hilo_kernel(const float* __restrict__ src,
                                 __nv_bfloat16* __restrict__ dhi,
                                 __nv_bfloat16* __restrict__ dlo,
                                 int Rows, int Ksrc, int Kp, int ld, int trans)
{
    size_t total = (size_t)Rows * Kp;
    for (size_t idx = (size_t)blockIdx.x * blockDim.x + threadIdx.x; idx < total;
         idx += (size_t)gridDim.x * blockDim.x) {
        int k   = (int)(idx % Kp);
        int row = (int)(idx / Kp);
        float v = 0.f;
        if (k < Ksrc) v = trans ? src[(size_t)k * ld + row] : src[(size_t)row * ld + k];
        __nv_bfloat16 h = __float2bfloat16(v);
        __nv_bfloat16 l = __float2bfloat16(v - __bfloat162float(h));
        dhi[idx] = h;
        dlo[idx] = l;
    }
}

// ---------------- HMMA bf16 3-pass GEMM ----------------
// C[M x Ntot] = A * B^T (+bias0+bias1). A: M x Kp (hi/lo), B: Ntot x Kp (hi/lo).
// Block tile 128x128, 256 threads (8 warps = 4m x 2n), K-chunk 32, cp.async double buffer.
#define KSTR 40                          // smem row stride in elements (80 B = 20 banks)
#define TILE_EL (128 * KSTR)             // 5120 elements per tile
#define STAGE_EL (4 * TILE_EL)           // Ahi, Alo, Bhi, Blo
#define GEMM_SMEM (2 * STAGE_EL * 2)     // bytes = 81920

__global__ __launch_bounds__(256, 1) void gemm_hmma_kernel(
    const __nv_bfloat16* __restrict__ Ahi, const __nv_bfloat16* __restrict__ Alo,
    const __nv_bfloat16* __restrict__ Bhi, const __nv_bfloat16* __restrict__ Blo,
    float* __restrict__ C, int Kp, int Ntot,
    const float* __restrict__ bias0, const float* __restrict__ bias1)
{
    extern __shared__ __nv_bfloat16 smb[];
    const uint32_t sbase = smem_u32(smb);

    const int tid  = threadIdx.x;
    const int lane = tid & 31;
    const int wid  = tid >> 5;
    const int wm   = wid & 3;            // 0..3
    const int wn   = wid >> 2;           // 0..1
    const int m0   = wm * 32;
    const int n0   = wn * 64;
    const int g    = lane >> 2;
    const int tg   = lane & 3;

    const int mblk = blockIdx.y * 128;
    const int nblk = blockIdx.x * 128;
    const int CH   = Kp >> 5;

    // per-thread staging map: 2 iterations cover 512 16B-chunks per tile
    const int r_a[2]  = { (tid >> 2),            ((tid + 256) >> 2) };
    const int c8_a[2] = { (tid & 3) * 8,         ((tid + 256) & 3) * 8 };

    float acc[2][8][4];
#pragma unroll
    for (int mt = 0; mt < 2; mt++)
#pragma unroll
        for (int nt = 0; nt < 8; nt++)
#pragma unroll
            for (int i = 0; i < 4; i++) acc[mt][nt][i] = 0.f;

    auto prefetch = [&](int c, int st) {
        const int k0 = c * 32;
        const uint32_t sA_hi = sbase + (uint32_t)(st * STAGE_EL) * 2;
        const uint32_t sA_lo = sA_hi + TILE_EL * 2;
        const uint32_t sB_hi = sA_lo + TILE_EL * 2;
        const uint32_t sB_lo = sB_hi + TILE_EL * 2;
#pragma unroll
        for (int i = 0; i < 2; i++) {
            const int r = r_a[i], c8 = c8_a[i];
            const uint32_t so = (uint32_t)(r * KSTR + c8) * 2;
            const size_t ga = (size_t)(mblk + r) * Kp + k0 + c8;
            const size_t gb = (size_t)(nblk + r) * Kp + k0 + c8;
            CP_ASYNC16(sA_hi + so, Ahi + ga);
            CP_ASYNC16(sA_lo + so, Alo + ga);
            CP_ASYNC16(sB_hi + so, Bhi + gb);
            CP_ASYNC16(sB_lo + so, Blo + gb);
        }
        CP_COMMIT();
    };

    prefetch(0, 0);

    for (int c = 0; c < CH; c++) {
        const int st = c & 1;
        CP_WAIT0();
        __syncthreads();
        if (c + 1 < CH) prefetch(c + 1, st ^ 1);

        const char* base = (const char*)smb + (size_t)(st * STAGE_EL) * 2;
        const char* pAhi = base;
        const char* pAlo = base + TILE_EL * 2;
        const char* pBhi = base + 2 * TILE_EL * 2;
        const char* pBlo = base + 3 * TILE_EL * 2;

#pragma unroll
        for (int kk = 0; kk < 2; kk++) {
            const int kb = kk * 32 + tg * 4;     // byte offset of k column pair
            uint32_t ah[2][4], al[2][4];
#pragma unroll
            for (int mt = 0; mt < 2; mt++) {
                const int r0 = (m0 + mt * 16 + g) * (KSTR * 2);
                const int r1 = r0 + 8 * (KSTR * 2);
                ah[mt][0] = *(const uint32_t*)(pAhi + r0 + kb);
                ah[mt][1] = *(const uint32_t*)(pAhi + r1 + kb);
                ah[mt][2] = *(const uint32_t*)(pAhi + r0 + kb + 16);
                ah[mt][3] = *(const uint32_t*)(pAhi + r1 + kb + 16);
                al[mt][0] = *(const uint32_t*)(pAlo + r0 + kb);
                al[mt][1] = *(const uint32_t*)(pAlo + r1 + kb);
                al[mt][2] = *(const uint32_t*)(pAlo + r0 + kb + 16);
                al[mt][3] = *(const uint32_t*)(pAlo + r1 + kb + 16);
            }
#pragma unroll
            for (int nt = 0; nt < 8; nt++) {
                const int rb = (n0 + nt * 8 + g) * (KSTR * 2);
                const uint32_t bh0 = *(const uint32_t*)(pBhi + rb + kb);
                const uint32_t bh1 = *(const uint32_t*)(pBhi + rb + kb + 16);
                const uint32_t bl0 = *(const uint32_t*)(pBlo + rb + kb);
                const uint32_t bl1 = *(const uint32_t*)(pBlo + rb + kb + 16);
#pragma unroll
                for (int mt = 0; mt < 2; mt++) {
                    mma_bf16(acc[mt][nt], ah[mt], bh0, bh1);
                    mma_bf16(acc[mt][nt], ah[mt], bl0, bl1);
                    mma_bf16(acc[mt][nt], al[mt], bh0, bh1);
                }
            }
        }
        __syncthreads();
    }

    // ---- epilogue ----
#pragma unroll
    for (int nt = 0; nt < 8; nt++) {
        const int col = nblk + n0 + nt * 8 + tg * 2;
        float b0 = 0.f, b1 = 0.f;
        if (bias0) { b0 += bias0[col]; b1 += bias0[col + 1]; }
        if (bias1) { b0 += bias1[col]; b1 += bias1[col + 1]; }
#pragma unroll
        for (int mt = 0; mt < 2; mt++) {
            const int row0 = mblk + m0 + mt * 16 + g;
            float2 v0 = make_float2(acc[mt][nt][0] + b0, acc[mt][nt][1] + b1);
            float2 v1 = make_float2(acc[mt][nt][2] + b0, acc[mt][nt][3] + b1);
            *reinterpret_cast<float2*>(C + (size_t)row0 * Ntot + col) = v0;
            *reinterpret_cast<float2*>(C + (size_t)(row0 + 8) * Ntot + col) = v1;
        }
    }
}

// ---------------- init recurrent state + barriers ----------------
__global__ void init_state_kernel(const float* __restrict__ h01, const float* __restrict__ c01,
                                  const float* __restrict__ h02, const float* __restrict__ c02)
{
    int i = blockIdx.x * blockDim.x + threadIdx.x;
    if (i < 16) { g_cnt[i] = 0; *((unsigned*)&g_gen[i]) = 0; }
    if (i >= B_ * H_) return;
    g_hbuf[(0 * 2 + 0) * B_ * H_ + i] = h01[i];
    g_cbuf[(0 * 2 + 0) * B_ * H_ + i] = c01[i];
    g_hbuf[(1 * 2 + 0) * B_ * H_ + i] = h02[i];
    g_cbuf[(1 * 2 + 0) * B_ * H_ + i] = c02[i];
}

// ---------------- packed fp32 helpers ----------------
__device__ __forceinline__ void fma2(unsigned long long& d, unsigned long long a, unsigned long long b) {
    asm("fma.rn.f32x2 %0, %1, %2, %0;" : "+l"(d) : "l"(a), "l"(b));
}
__device__ __forceinline__ float2 unpack2(unsigned long long v) {
    float2 f;
    asm("mov.b64 {%0, %1}, %2;" : "=f"(f.x), "=f"(f.y) : "l"(v));
    return f;
}

// ---------------- persistent LSTM scan (unchanged from R3) ----------------
#define WJT 32
#define HS_STRIDE 260
#define SCAN_SMEM ((5 * WJT * 256 + 2 * 16 * HS_STRIDE) * 4)

__global__ __launch_bounds__(256) void lstm_scan_kernel(
    const float* __restrict__ Wall1, const float* __restrict__ Wd1, const float* __restrict__ Wdb1,
    const float* __restrict__ Wall2, const float* __restrict__ Wd2, const float* __restrict__ Wdb2,
    const float* __restrict__ tsp)
{
    extern __shared__ float sm[];
    float* wsm = sm;
    float* hsm = sm + 5 * WJT * 256;
    float* csm = hsm + 16 * HS_STRIDE;

    const int bid   = blockIdx.x;
    const int lstm  = bid >> 6;
    const int btile = (bid >> 3) & 7;
    const int jt    = bid & 7;
    const int b0 = btile * 16;
    const int j0 = jt * WJT;
    const int grp = lstm * 8 + btile;

    const float* Wall = lstm ? Wall2 : Wall1;
    const float* Wd   = lstm ? Wd2   : Wd1;
    const float* Wdb  = lstm ? Wdb2  : Wdb1;
    const float* ux   = lstm ? g_ux2 : g_ux1;
    float*       outp = lstm ? g_out2 : g_out1;

    const int tid = threadIdx.x;

    for (int idx = tid; idx < 5 * WJT * 64; idx += 256) {
        int g   = idx >> 11;
        int rem = idx & 2047;
        int lj  = rem >> 6;
        int k4  = (rem & 63) << 2;
        const float* src = (g < 4) ? (Wall + (size_t)(g * H_ + j0 + lj) * H_ + k4)
                                   : (Wd   + (size_t)(j0 + lj) * H_ + k4);
        *reinterpret_cast<float4*>(&wsm[((g << 5) + lj) * 256 + k4]) =
            *reinterpret_cast<const float4*>(src);
    }

    const int bi = tid & 15;
    const int jj = tid >> 4;
    const int b  = b0 + bi;
    const int jA = j0 + jj;
    const int jB = jA + 16;
    const float wdbA = Wdb[jA];
    const float wdbB = Wdb[jB];

    const float* wA[5];
    const float* wB[5];
#pragma unroll
    for (int g = 0; g < 5; g++) {
        wA[g] = &wsm[((g << 5) + jj) * 256];
        wB[g] = &wsm[((g << 5) + jj + 16) * 256];
    }

    for (int s = 0; s < SEQ_; s++) {
        const int pr = s & 1;
        const float* hsrc = g_hbuf + (size_t)(lstm * 2 + pr) * B_ * H_;
        const float* csrc = g_cbuf + (size_t)(lstm * 2 + pr) * B_ * H_;
        for (int idx = tid; idx < 16 * 64; idx += 256) {
            int r  = idx >> 6;
            int c4 = (idx & 63) << 2;
            *reinterpret_cast<float4*>(&hsm[r * HS_STRIDE + c4]) =
                *reinterpret_cast<const float4*>(&hsrc[(size_t)(b0 + r) * H_ + c4]);
            *reinterpret_cast<float4*>(&csm[r * HS_STRIDE + c4]) =
                *reinterpret_cast<const float4*>(&csrc[(size_t)(b0 + r) * H_ + c4]);
        }
        __syncthreads();

        const size_t row = (size_t)b * SEQ_ + s;
        const float t = tsp[row];
        const float* uxp = ux + row * G4H;
        float uxA[4], uxB[4];
#pragma unroll
        for (int g = 0; g < 4; g++) { uxA[g] = uxp[g * H_ + jA]; uxB[g] = uxp[g * H_ + jB]; }

        unsigned long long acc[10];
#pragma unroll
        for (int i = 0; i < 10; i++) acc[i] = 0ULL;
        const float* hrow = &hsm[bi * HS_STRIDE];
        const float* crow = &csm[bi * HS_STRIDE];

#pragma unroll 4
        for (int k = 0; k < H_; k += 4) {
            ulonglong2 h2 = *reinterpret_cast<const ulonglong2*>(&hrow[k]);
            ulonglong2 c2 = *reinterpret_cast<const ulonglong2*>(&crow[k]);
#pragma unroll
            for (int g = 0; g < 4; g++) {
                ulonglong2 w2 = *reinterpret_cast<const ulonglong2*>(&wA[g][k]);
                fma2(acc[g], h2.x, w2.x);
                fma2(acc[g], h2.y, w2.y);
                ulonglong2 v2 = *reinterpret_cast<const ulonglong2*>(&wB[g][k]);
                fma2(acc[5 + g], h2.x, v2.x);
                fma2(acc[5 + g], h2.y, v2.y);
            }
            ulonglong2 d2 = *reinterpret_cast<const ulonglong2*>(&wA[4][k]);
            fma2(acc[4], c2.x, d2.x);
            fma2(acc[4], c2.y, d2.y);
            ulonglong2 e2 = *reinterpret_cast<const ulonglong2*>(&wB[4][k]);
            fma2(acc[9], c2.x, e2.x);
            fma2(acc[9], c2.y, e2.y);
        }

        float* hdst = g_hbuf + (size_t)(lstm * 2 + (1 - pr)) * B_ * H_;
        float* cdst = g_cbuf + (size_t)(lstm * 2 + (1 - pr)) * B_ * H_;
#pragma unroll
        for (int half = 0; half < 2; half++) {
            const int base = half * 5;
            float2 vf = unpack2(acc[base + 0]);
            float2 vi = unpack2(acc[base + 1]);
            float2 vo = unpack2(acc[base + 2]);
            float2 vc = unpack2(acc[base + 3]);
            float2 vd = unpack2(acc[base + 4]);
            const float af = vf.x + vf.y;
            const float ai = vi.x + vi.y;
            const float ao = vo.x + vo.y;
            const float ag = vc.x + vc.y;
            const float ad = vd.x + vd.y;
            const int   j   = half ? jB : jA;
            const float wdb = half ? wdbB : wdbA;
            const float* uxv = half ? uxB : uxA;

            const float cs1  = tanhf(ad + wdb);
            const float ccur = crow[j];
            const float cadj = ccur - cs1 + cs1 * t;
            const float gf = 1.f / (1.f + expf(-(af + uxv[0])));
            const float gi = 1.f / (1.f + expf(-(ai + uxv[1])));
            const float go = 1.f / (1.f + expf(-(ao + uxv[2])));
            const float gc = 1.f / (1.f + expf(-(ag + uxv[3])));
            const float cnew = gf * cadj + gi * gc;
            const float hnew = go * tanhf(cnew);

            hdst[(size_t)b * H_ + j] = hnew;
            cdst[(size_t)b * H_ + j] = cnew;
            outp[row * H_ + j] = hnew;
        }

        __threadfence();
        __syncthreads();
        if (tid == 0) {
            unsigned arrived = atomicAdd(&g_cnt[grp], 1u);
            if (arrived == 7u) {
                g_cnt[grp] = 0;
                __threadfence();
                atomicAdd((unsigned*)&g_gen[grp], 1u);
            }
            while (g_gen[grp] < (unsigned)(s + 1)) { __nanosleep(32); }
        }
        __syncthreads();
        __threadfence();
    }
}

// ---------------- attention softmax ----------------
__global__ void attn_softmax_kernel(const float* __restrict__ wa)
{
    const int b    = blockIdx.x;
    const int tid  = threadIdx.x;
    const int lane = tid & 31;
    const int w    = tid >> 5;
    __shared__ float Es[SEQ_];
    __shared__ float mx, smv;

    for (int s = w; s < SEQ_; s += 8) {
        const float* o = g_out1 + ((size_t)b * SEQ_ + s) * H_;
        float sum = 0.f;
        for (int h = lane; h < H_; h += 32) sum += o[h] * wa[h];
#pragma unroll
        for (int off = 16; off; off >>= 1) sum += __shfl_xor_sync(0xffffffffu, sum, off);
        if (lane == 0) Es[s] = sum;
    }
    __syncthreads();
    if (tid == 0) {
        float m = -1e30f;
        for (int s = 0; s < SEQ_; s++) m = fmaxf(m, Es[s]);
        mx = m;
    }
    __syncthreads();
    if (tid < SEQ_) Es[tid] = expf(Es[tid] - mx);
    __syncthreads();
    if (tid == 0) {
        float t = 0.f;
        for (int s = 0; s < SEQ_; s++) t += Es[s];
        smv = t;
    }
    __syncthreads();
    if (tid < SEQ_) g_alpha[(size_t)b * SEQ_ + tid] = Es[tid] / smv;
}

// ---------------- ctx ----------------
__global__ void ctx_kernel()
{
    const int b = blockIdx.x;
    const int d = threadIdx.x;
    float acc = 0.f;
    for (int s = 0; s < SEQ_; s++) {
        size_t r = (size_t)b * SEQ_ + s;
        acc += g_embedded[r * D_ + d] * tanhf(g_beta[r * H_ + d]) * g_alpha[r];
    }
    g_ctx[(size_t)b * D_ + d] = acc;
}

// ---------------- output head ----------------
__global__ void out_kernel(const float* __restrict__ Wout, float* __restrict__ out)
{
    const int b = blockIdx.x;
    const int n = threadIdx.x;
    __shared__ float cx[D_];
    for (int d = threadIdx.x; d < D_; d += blockDim.x) cx[d] = g_ctx[(size_t)b * D_ + d];
    __syncthreads();
    float acc = 0.f;
    const float* wr = Wout + (size_t)n * H_;
#pragma unroll 8
    for (int d = 0; d < D_; d++) acc = fmaf(cx[d], wr[d], acc);
    out[(size_t)b * NCLS_ + n] = acc;
}

// ---------------- host launcher ----------------
extern "C" void kernel_launch(void* const* d_in, const int* in_sizes, int n_in,
                              void* d_out, int out_size)
{
    const float* inputs = (const float*)d_in[0];
    const float* tsp    = (const float*)d_in[1];
    const float* emb    = (const float*)d_in[2];
    const float* Wall1  = (const float*)d_in[3];
    const float* Wall1b = (const float*)d_in[4];
    const float* Uall1  = (const float*)d_in[5];
    const float* Uall1b = (const float*)d_in[6];
    const float* Wd1    = (const float*)d_in[7];
    const float* Wd1b   = (const float*)d_in[8];
    const float* Wall2  = (const float*)d_in[9];
    const float* Wall2b = (const float*)d_in[10];
    const float* Uall2  = (const float*)d_in[11];
    const float* Uall2b = (const float*)d_in[12];
    const float* Wd2    = (const float*)d_in[13];
    const float* Wd2b   = (const float*)d_in[14];
    const float* wa     = (const float*)d_in[15];
    const float* Wb     = (const float*)d_in[16];
    const float* Wout   = (const float*)d_in[17];
    const float* h01    = (const float*)d_in[18];
    const float* c01    = (const float*)d_in[19];
    const float* h02    = (const float*)d_in[20];
    const float* c02    = (const float*)d_in[21];
    float* out = (float*)d_out;

    void *p_emb, *p_ux1, *p_ux2, *p_out2, *p_beta;
    cudaGetSymbolAddress(&p_emb,  g_embedded);
    cudaGetSymbolAddress(&p_ux1,  g_ux1);
    cudaGetSymbolAddress(&p_ux2,  g_ux2);
    cudaGetSymbolAddress(&p_out2, g_out2);
    cudaGetSymbolAddress(&p_beta, g_beta);

    void *pa_in_hi, *pa_in_lo, *pb_emb_hi, *pb_emb_lo, *pa_e_hi, *pa_e_lo;
    void *pb_u1_hi, *pb_u1_lo, *pb_u2_hi, *pb_u2_lo, *pb_wb_hi, *pb_wb_lo;
    void *pa_o2_hi, *pa_o2_lo;
    cudaGetSymbolAddress(&pa_in_hi, ga_in_hi);
    cudaGetSymbolAddress(&pa_in_lo, ga_in_lo);
    cudaGetSymbolAddress(&pb_emb_hi, gb_emb_hi);
    cudaGetSymbolAddress(&pb_emb_lo, gb_emb_lo);
    cudaGetSymbolAddress(&pa_e_hi, ga_e_hi);
    cudaGetSymbolAddress(&pa_e_lo, ga_e_lo);
    cudaGetSymbolAddress(&pb_u1_hi, gb_u1_hi);
    cudaGetSymbolAddress(&pb_u1_lo, gb_u1_lo);
    cudaGetSymbolAddress(&pb_u2_hi, gb_u2_hi);
    cudaGetSymbolAddress(&pb_u2_lo, gb_u2_lo);
    cudaGetSymbolAddress(&pb_wb_hi, gb_wb_hi);
    cudaGetSymbolAddress(&pb_wb_lo, gb_wb_lo);
    cudaGetSymbolAddress(&pa_o2_hi, ga_o2_hi);
    cudaGetSymbolAddress(&pa_o2_lo, ga_o2_lo);

    cudaFuncSetAttribute(lstm_scan_kernel,
                         cudaFuncAttributeMaxDynamicSharedMemorySize, SCAN_SMEM);
    cudaFuncSetAttribute(gemm_hmma_kernel,
                         cudaFuncAttributeMaxDynamicSharedMemorySize, GEMM_SMEM);

    const int M = B_ * SEQ_;   // 25600

    // ---- operand prep (hi/lo bf16, row-major) ----
    conv_hilo_kernel<<<4096, 256>>>(inputs, (__nv_bfloat16*)pa_in_hi, (__nv_bfloat16*)pa_in_lo,
                                    M, VOCAB_, KP_IN, VOCAB_, 0);
    conv_hilo_kernel<<<512, 256>>>(emb, (__nv_bfloat16*)pb_emb_hi, (__nv_bfloat16*)pb_emb_lo,
                                   D_, VOCAB_, KP_IN, D_, 1);
    conv_hilo_kernel<<<512, 256>>>(Uall1, (__nv_bfloat16*)pb_u1_hi, (__nv_bfloat16*)pb_u1_lo,
                                   G4H, H_, H_, H_, 0);
    conv_hilo_kernel<<<512, 256>>>(Uall2, (__nv_bfloat16*)pb_u2_hi, (__nv_bfloat16*)pb_u2_lo,
                                   G4H, H_, H_, H_, 0);
    conv_hilo_kernel<<<256, 256>>>(Wb, (__nv_bfloat16*)pb_wb_hi, (__nv_bfloat16*)pb_wb_lo,
                                   H_, H_, H_, H_, 0);

    // 1) embedded = inputs @ emb     [25600 x 256], K=1408
    gemm_hmma_kernel<<<dim3(D_ / 128, M / 128), 256, GEMM_SMEM>>>(
        (const __nv_bfloat16*)pa_in_hi, (const __nv_bfloat16*)pa_in_lo,
        (const __nv_bfloat16*)pb_emb_hi, (const __nv_bfloat16*)pb_emb_lo,
        (float*)p_emb, KP_IN, D_, nullptr, nullptr);

    // embedded -> hi/lo (A for ux GEMMs)
    conv_hilo_kernel<<<2048, 256>>>((const float*)p_emb,
                                    (__nv_bfloat16*)pa_e_hi, (__nv_bfloat16*)pa_e_lo,
                                    M, D_, D_, D_, 0);

    // 2) ux = embedded @ Uall^T + (Uall_b + Wall_b)    [25600 x 1024], K=256
    gemm_hmma_kernel<<<dim3(G4H / 128, M / 128), 256, GEMM_SMEM>>>(
        (const __nv_bfloat16*)pa_e_hi, (const __nv_bfloat16*)pa_e_lo,
        (const __nv_bfloat16*)pb_u1_hi, (const __nv_bfloat16*)pb_u1_lo,
        (float*)p_ux1, H_, G4H, Uall1b, Wall1b);
    gemm_hmma_kernel<<<dim3(G4H / 128, M / 128), 256, GEMM_SMEM>>>(
        (const __nv_bfloat16*)pa_e_hi, (const __nv_bfloat16*)pa_e_lo,
        (const __nv_bfloat16*)pb_u2_hi, (const __nv_bfloat16*)pb_u2_lo,
        (float*)p_ux2, H_, G4H, Uall2b, Wall2b);

    // 3) recurrent scan
    init_state_kernel<<<(B_ * H_ + 255) / 256, 256>>>(h01, c01, h02, c02);
    lstm_scan_kernel<<<128, 256, SCAN_SMEM>>>(Wall1, Wd1, Wd1b, Wall2, Wd2, Wd2b, tsp);

    // 4) attention weights
    attn_softmax_kernel<<<B_, 256>>>(wa);

    // 5) beta = out2 @ Wb^T   [25600 x 256], K=256
    conv_hilo_kernel<<<2048, 256>>>((const float*)p_out2,
                                    (__nv_bfloat16*)pa_o2_hi, (__nv_bfloat16*)pa_o2_lo,
                                    M, H_, H_, H_, 0);
    gemm_hmma_kernel<<<dim3(H_ / 128, M / 128), 256, GEMM_SMEM>>>(
        (const __nv_bfloat16*)pa_o2_hi, (const __nv_bfloat16*)pa_o2_lo,
        (const __nv_bfloat16*)pb_wb_hi, (const __nv_bfloat16*)pb_wb_lo,
        (float*)p_beta, H_, H_, nullptr, nullptr);

    // 6) context + output head
    ctx_kernel<<<B_, 256>>>();
    out_kernel<<<B_, 128>>>(Wout, out);
}